// round 1
// baseline (speedup 1.0000x reference)
#include <cuda_runtime.h>
#include <cuda_bf16.h>
#include <math.h>

// Problem constants
#define BB   16
#define SS   512
#define WW   8
#define DQ   256
#define DIN  512
#define DOUT 512

// Scratch (device globals: allocation-free per harness rules)
static __device__ float g_Q[(long long)BB*SS*WW*DIN];   // 33.5M floats; reused as Z1 after scores
static __device__ float g_K[(long long)BB*SS*DIN];      // 4.2M
static __device__ float g_V[(long long)BB*SS*DIN];      // 4.2M
static __device__ float g_P[(long long)BB*SS*WW*SS];    // 33.5M (softmaxed probs, row-major [b][(q,w)][k])
static __device__ unsigned char g_cmask[BB*SS*WW];
static __device__ unsigned char g_words[BB*SS];
static __device__ int g_mask_mode;  // 0 = float32, 1 = int32, 2 = uint8/bool

// ---------------------------------------------------------------------------
// Mask dtype detection: bool arrays may arrive as f32 (0.0/1.0), i32 (0/1),
// or raw bytes. Classify from the first 1024 32-bit words (always >= 4KB of
// valid buffer for 65536 elements in any of the three encodings).
// ---------------------------------------------------------------------------
__global__ void detect_mask_kernel(const unsigned int* __restrict__ m) {
    if (blockIdx.x == 0 && threadIdx.x == 0) {
        bool all01 = true, allf = true;
        for (int i = 0; i < 1024; i++) {
            unsigned int v = m[i];
            if (!(v == 0u || v == 1u)) all01 = false;
            if (!(v == 0u || v == 0x3F800000u)) allf = false;
        }
        g_mask_mode = all01 ? 1 : (allf ? 0 : 2);
    }
}

__global__ void normalize_mask_kernel(const void* __restrict__ m,
                                      unsigned char* __restrict__ cmask,
                                      unsigned char* __restrict__ words) {
    int idx = blockIdx.x * blockDim.x + threadIdx.x;  // over B*S
    if (idx >= BB * SS) return;
    int mode = g_mask_mode;
    unsigned char any = 0;
    #pragma unroll
    for (int w = 0; w < WW; w++) {
        int e = idx * WW + w;
        unsigned char v;
        if (mode == 1)      v = (((const int*)m)[e] != 0);
        else if (mode == 0) v = (((const float*)m)[e] != 0.0f);
        else                v = (((const unsigned char*)m)[e] != 0);
        cmask[e] = v;
        any |= v;
    }
    words[idx] = any;
}

// ---------------------------------------------------------------------------
// Generic SGEMM: C[M,N] = A[M,K] @ B[K,N] (+ bias[N]), optionally batched via
// grid.z with element strides. 128x128 block tile, k-chunk 8, 256 threads,
// 8x8 per-thread micro-tile. All dims here are multiples of the tile sizes.
// ---------------------------------------------------------------------------
__global__ __launch_bounds__(256)
void sgemm_bias(const float* __restrict__ A, const float* __restrict__ Bm,
                const float* __restrict__ bias, float* __restrict__ C,
                int M, int N, int K,
                long long sA, long long sB, long long sC) {
    A  += (long long)blockIdx.z * sA;
    Bm += (long long)blockIdx.z * sB;
    C  += (long long)blockIdx.z * sC;

    __shared__ float As[8][132];  // padded: conflict-free transposed stores
    __shared__ float Bs[8][128];

    const int tid = threadIdx.x;
    const int tx = tid & 15, ty = tid >> 4;
    const int row0 = blockIdx.y * 128, col0 = blockIdx.x * 128;

    float acc[8][8];
    #pragma unroll
    for (int i = 0; i < 8; i++)
        #pragma unroll
        for (int j = 0; j < 8; j++) acc[i][j] = 0.0f;

    const int arow = tid >> 1, acol4 = (tid & 1) * 4;   // A tile [128][8]
    const int brow = tid >> 5, bcol4 = (tid & 31) * 4;  // B tile [8][128]

    for (int k0 = 0; k0 < K; k0 += 8) {
        float4 a4 = *(const float4*)&A[(long long)(row0 + arow) * K + k0 + acol4];
        As[acol4 + 0][arow] = a4.x;
        As[acol4 + 1][arow] = a4.y;
        As[acol4 + 2][arow] = a4.z;
        As[acol4 + 3][arow] = a4.w;
        float4 b4 = *(const float4*)&Bm[(long long)(k0 + brow) * N + col0 + bcol4];
        *(float4*)&Bs[brow][bcol4] = b4;
        __syncthreads();

        #pragma unroll
        for (int k = 0; k < 8; k++) {
            float ra[8], rb[8];
            *(float4*)&ra[0] = *(const float4*)&As[k][ty * 8];
            *(float4*)&ra[4] = *(const float4*)&As[k][ty * 8 + 4];
            *(float4*)&rb[0] = *(const float4*)&Bs[k][tx * 8];
            *(float4*)&rb[4] = *(const float4*)&Bs[k][tx * 8 + 4];
            #pragma unroll
            for (int i = 0; i < 8; i++)
                #pragma unroll
                for (int j = 0; j < 8; j++)
                    acc[i][j] = fmaf(ra[i], rb[j], acc[i][j]);
        }
        __syncthreads();
    }

    float bb0[8];
    #pragma unroll
    for (int j = 0; j < 8; j++)
        bb0[j] = bias ? bias[col0 + tx * 8 + j] : 0.0f;

    #pragma unroll
    for (int i = 0; i < 8; i++) {
        long long r = row0 + ty * 8 + i;
        float4 v0, v1;
        v0.x = acc[i][0] + bb0[0]; v0.y = acc[i][1] + bb0[1];
        v0.z = acc[i][2] + bb0[2]; v0.w = acc[i][3] + bb0[3];
        v1.x = acc[i][4] + bb0[4]; v1.y = acc[i][5] + bb0[5];
        v1.z = acc[i][6] + bb0[6]; v1.w = acc[i][7] + bb0[7];
        *(float4*)&C[r * N + col0 + tx * 8]     = v0;
        *(float4*)&C[r * N + col0 + tx * 8 + 4] = v1;
    }
}

// ---------------------------------------------------------------------------
// Fused scores kernel. Block = (batch b, 4 query positions) -> full 32x512
// score tile (rows = (q_local, w), cols = all 512 keys). Computes Q.K^T,
// masks, softmaxes over keys in-register (each row lives in one warp), then
// writes the contiguous prob matrix P (for the P@V GEMM) and the strided
// att output [b][q][k][w].
// Thread map: 256 thr = 8 warps; warp ty owns rows ty*4..ty*4+3 fully;
// lane tx owns columns {g*128 + tx*4 + j : g<4, j<4}.
// ---------------------------------------------------------------------------
__global__ __launch_bounds__(256)
void attn_scores_kernel(const float* __restrict__ Q, const float* __restrict__ Kmat,
                        const unsigned char* __restrict__ cmask,
                        const unsigned char* __restrict__ words,
                        float* __restrict__ P, float* __restrict__ att) {
    const int b = blockIdx.y;
    const int q0 = blockIdx.x * 4;

    const float* Qb = Q    + ((long long)(b * SS + q0) * WW) * DIN;  // 32 rows x 512
    const float* Kb = Kmat + (long long)b * SS * DIN;                // 512 rows x 512

    __shared__ float Qs[16][33];
    __shared__ float Ks[16][516];

    const int tid = threadIdx.x;
    const int tx = tid & 31, ty = tid >> 5;

    float acc[4][16];
    #pragma unroll
    for (int i = 0; i < 4; i++)
        #pragma unroll
        for (int j = 0; j < 16; j++) acc[i][j] = 0.0f;

    for (int d0 = 0; d0 < DIN; d0 += 16) {
        // Qs: 32 rows x 16 d (transposed)
        {
            int r = tid >> 3, c2 = (tid & 7) * 2;
            float2 v = *(const float2*)&Qb[(long long)r * DIN + d0 + c2];
            Qs[c2][r] = v.x;
            Qs[c2 + 1][r] = v.y;
        }
        // Ks: 512 keys x 16 d (transposed)
        #pragma unroll
        for (int it = 0; it < 8; it++) {
            int s = tid + it * 256;          // 2048 float4 slots
            int kk = s >> 2, dg = (s & 3) * 4;
            float4 v = *(const float4*)&Kb[(long long)kk * DIN + d0 + dg];
            Ks[dg + 0][kk] = v.x;
            Ks[dg + 1][kk] = v.y;
            Ks[dg + 2][kk] = v.z;
            Ks[dg + 3][kk] = v.w;
        }
        __syncthreads();

        #pragma unroll
        for (int d = 0; d < 16; d++) {
            float qv[4];
            #pragma unroll
            for (int i = 0; i < 4; i++) qv[i] = Qs[d][ty * 4 + i];
            #pragma unroll
            for (int g = 0; g < 4; g++) {
                float4 kv = *(const float4*)&Ks[d][g * 128 + tx * 4];
                #pragma unroll
                for (int i = 0; i < 4; i++) {
                    acc[i][g * 4 + 0] = fmaf(qv[i], kv.x, acc[i][g * 4 + 0]);
                    acc[i][g * 4 + 1] = fmaf(qv[i], kv.y, acc[i][g * 4 + 1]);
                    acc[i][g * 4 + 2] = fmaf(qv[i], kv.z, acc[i][g * 4 + 2]);
                    acc[i][g * 4 + 3] = fmaf(qv[i], kv.w, acc[i][g * 4 + 3]);
                }
            }
        }
        __syncthreads();
    }

    const float scale = 1.0f / sqrtf((float)DIN);
    // Key-side mask bits for this lane's 16 columns (same for every row)
    unsigned char wmk[16];
    #pragma unroll
    for (int g = 0; g < 4; g++)
        #pragma unroll
        for (int j = 0; j < 4; j++)
            wmk[g * 4 + j] = words[b * SS + g * 128 + tx * 4 + j];

    #pragma unroll
    for (int i = 0; i < 4; i++) {
        int r = ty * 4 + i;                             // 0..31 within tile
        int gr = (b * SS + q0) * WW + r;                // global (q,w) row
        unsigned char cm = cmask[gr];

        float mx = -3.0e38f;
        #pragma unroll
        for (int c = 0; c < 16; c++) {
            float s = acc[i][c] * scale;
            s = (cm && wmk[c]) ? s : -1e9f;
            acc[i][c] = s;
            mx = fmaxf(mx, s);
        }
        #pragma unroll
        for (int o = 16; o > 0; o >>= 1)
            mx = fmaxf(mx, __shfl_xor_sync(0xffffffffu, mx, o));

        float sum = 0.0f;
        #pragma unroll
        for (int c = 0; c < 16; c++) {
            float e = __expf(acc[i][c] - mx);
            acc[i][c] = e;
            sum += e;
        }
        #pragma unroll
        for (int o = 16; o > 0; o >>= 1)
            sum += __shfl_xor_sync(0xffffffffu, sum, o);
        float inv = 1.0f / sum;

        // P: contiguous [b][(q,w)][k] (coalesced float4 per g-group)
        long long prow = ((long long)b * (SS * WW) + (q0 * WW + r)) * SS;
        #pragma unroll
        for (int g = 0; g < 4; g++) {
            float4 o4;
            o4.x = acc[i][g * 4 + 0] * inv;
            o4.y = acc[i][g * 4 + 1] * inv;
            o4.z = acc[i][g * 4 + 2] * inv;
            o4.w = acc[i][g * 4 + 3] * inv;
            *(float4*)&P[prow + g * 128 + tx * 4] = o4;
            acc[i][g * 4 + 0] = o4.x; acc[i][g * 4 + 1] = o4.y;
            acc[i][g * 4 + 2] = o4.z; acc[i][g * 4 + 3] = o4.w;
        }
        // att: [b][q][k][w] (strided; element stores)
        if (att) {
            int q = q0 + (r >> 3), w = r & 7;
            long long abase = (((long long)b * SS + q) * SS) * WW + w;
            #pragma unroll
            for (int g = 0; g < 4; g++)
                #pragma unroll
                for (int j = 0; j < 4; j++) {
                    int k = g * 128 + tx * 4 + j;
                    att[abase + (long long)k * WW] = acc[i][g * 4 + j];
                }
        }
    }
}

// ---------------------------------------------------------------------------
extern "C" void kernel_launch(void* const* d_in, const int* in_sizes, int n_in,
                              void* d_out, int out_size) {
    const float* query = (const float*)d_in[0];
    const float* data  = (const float*)d_in[1];
    const void*  maskr = d_in[2];
    const float* Wq = (const float*)d_in[3];
    const float* bq = (const float*)d_in[4];
    const float* Wk = (const float*)d_in[5];
    const float* bk = (const float*)d_in[6];
    const float* Wv = (const float*)d_in[7];
    const float* bv = (const float*)d_in[8];
    const float* Wz = (const float*)d_in[9];
    const float* bz = (const float*)d_in[10];

    float* out = (float*)d_out;
    const long long zs_elems  = (long long)BB * SS * WW * DOUT;  // 33,554,432
    const long long att_elems = (long long)BB * SS * SS * WW;    // 33,554,432
    float* att = ((long long)out_size >= zs_elems + att_elems) ? out + zs_elems : nullptr;

    float *Qp, *Kp, *Vp, *Pp;
    unsigned char *cm, *wm;
    cudaGetSymbolAddress((void**)&Qp, g_Q);
    cudaGetSymbolAddress((void**)&Kp, g_K);
    cudaGetSymbolAddress((void**)&Vp, g_V);
    cudaGetSymbolAddress((void**)&Pp, g_P);
    cudaGetSymbolAddress((void**)&cm, g_cmask);
    cudaGetSymbolAddress((void**)&wm, g_words);

    // 0) classify mask dtype, normalize to bytes + key-side any() mask
    detect_mask_kernel<<<1, 1>>>((const unsigned int*)maskr);
    normalize_mask_kernel<<<(BB * SS + 255) / 256, 256>>>(maskr, cm, wm);

    // 1) Q projection: [65536,256] @ [256,512] + bq -> g_Q
    sgemm_bias<<<dim3(DIN / 128, (BB * SS * WW) / 128, 1), 256>>>(
        query, Wq, bq, Qp, BB * SS * WW, DIN, DQ, 0, 0, 0);
    // 2) K projection: [8192,512] @ [512,512] + bk -> g_K
    sgemm_bias<<<dim3(DIN / 128, (BB * SS) / 128, 1), 256>>>(
        data, Wk, bk, Kp, BB * SS, DIN, DIN, 0, 0, 0);
    // 3) V projection -> g_V
    sgemm_bias<<<dim3(DOUT / 128, (BB * SS) / 128, 1), 256>>>(
        data, Wv, bv, Vp, BB * SS, DOUT, DIN, 0, 0, 0);

    // 4) scores + mask + softmax -> P (and att region of d_out)
    attn_scores_kernel<<<dim3(SS / 4, BB), 256>>>(Qp, Kp, cm, wm, Pp, att);

    // 5) Z1[b] = P[b] @ V[b]   (batched over grid.z; reuse g_Q as Z1)
    sgemm_bias<<<dim3(DOUT / 128, (SS * WW) / 128, BB), 256>>>(
        Pp, Vp, nullptr, Qp, SS * WW, DOUT, SS,
        (long long)SS * WW * SS, (long long)SS * DIN, (long long)SS * WW * DOUT);

    // 6) zs = Z1 @ Wz + bz -> d_out (first zs_elems floats)
    sgemm_bias<<<dim3(DOUT / 128, (BB * SS * WW) / 128, 1), 256>>>(
        Qp, Wz, bz, out, BB * SS * WW, DOUT, DOUT, 0, 0, 0);
}

// round 2
// speedup vs baseline: 1.0013x; 1.0013x over previous
#include <cuda_runtime.h>
#include <cuda_bf16.h>
#include <math.h>

// Problem constants
#define BB   16
#define SS   512
#define WW   8
#define DQ   256
#define DIN  512
#define DOUT 512

// Scratch (device globals: allocation-free per harness rules)
static __device__ float g_Q[(long long)BB*SS*WW*DIN];   // 33.5M floats; reused as Z1 after scores
static __device__ float g_K[(long long)BB*SS*DIN];      // 4.2M
static __device__ float g_V[(long long)BB*SS*DIN];      // 4.2M
static __device__ float g_P[(long long)BB*SS*WW*SS];    // 33.5M (softmaxed probs, row-major [b][(q,w)][k])
static __device__ unsigned char g_cmask[BB*SS*WW];
static __device__ unsigned char g_words[BB*SS];
static __device__ int g_mask_mode;  // 0 = float32, 1 = int32, 2 = uint8/bool

// ---------------------------------------------------------------------------
// Mask dtype detection: bool arrays may arrive as f32 (0.0/1.0), i32 (0/1),
// or raw bytes. Classify from the first 1024 32-bit words (always >= 4KB of
// valid buffer for 65536 elements in any of the three encodings).
// ---------------------------------------------------------------------------
__global__ void detect_mask_kernel(const unsigned int* __restrict__ m) {
    if (blockIdx.x == 0 && threadIdx.x == 0) {
        bool all01 = true, allf = true;
        for (int i = 0; i < 1024; i++) {
            unsigned int v = m[i];
            if (!(v == 0u || v == 1u)) all01 = false;
            if (!(v == 0u || v == 0x3F800000u)) allf = false;
        }
        g_mask_mode = all01 ? 1 : (allf ? 0 : 2);
    }
}

__global__ void normalize_mask_kernel(const void* __restrict__ m,
                                      unsigned char* __restrict__ cmask,
                                      unsigned char* __restrict__ words) {
    int idx = blockIdx.x * blockDim.x + threadIdx.x;  // over B*S
    if (idx >= BB * SS) return;
    int mode = g_mask_mode;
    unsigned char any = 0;
    #pragma unroll
    for (int w = 0; w < WW; w++) {
        int e = idx * WW + w;
        unsigned char v;
        if (mode == 1)      v = (((const int*)m)[e] != 0);
        else if (mode == 0) v = (((const float*)m)[e] != 0.0f);
        else                v = (((const unsigned char*)m)[e] != 0);
        cmask[e] = v;
        any |= v;
    }
    words[idx] = any;
}

// ---------------------------------------------------------------------------
// Generic SGEMM: C[M,N] = A[M,K] @ B[K,N] (+ bias[N]), optionally batched via
// grid.z with element strides. 128x128 block tile, k-chunk 8, 256 threads,
// 8x8 per-thread micro-tile. All dims here are multiples of the tile sizes.
// ---------------------------------------------------------------------------
__global__ __launch_bounds__(256)
void sgemm_bias(const float* __restrict__ A, const float* __restrict__ Bm,
                const float* __restrict__ bias, float* __restrict__ C,
                int M, int N, int K,
                long long sA, long long sB, long long sC) {
    A  += (long long)blockIdx.z * sA;
    Bm += (long long)blockIdx.z * sB;
    C  += (long long)blockIdx.z * sC;

    __shared__ float As[8][132];  // padded: conflict-free transposed stores
    __shared__ float Bs[8][128];

    const int tid = threadIdx.x;
    const int tx = tid & 15, ty = tid >> 4;
    const int row0 = blockIdx.y * 128, col0 = blockIdx.x * 128;

    float acc[8][8];
    #pragma unroll
    for (int i = 0; i < 8; i++)
        #pragma unroll
        for (int j = 0; j < 8; j++) acc[i][j] = 0.0f;

    const int arow = tid >> 1, acol4 = (tid & 1) * 4;   // A tile [128][8]
    const int brow = tid >> 5, bcol4 = (tid & 31) * 4;  // B tile [8][128]

    for (int k0 = 0; k0 < K; k0 += 8) {
        float4 a4 = *(const float4*)&A[(long long)(row0 + arow) * K + k0 + acol4];
        As[acol4 + 0][arow] = a4.x;
        As[acol4 + 1][arow] = a4.y;
        As[acol4 + 2][arow] = a4.z;
        As[acol4 + 3][arow] = a4.w;
        float4 b4 = *(const float4*)&Bm[(long long)(k0 + brow) * N + col0 + bcol4];
        *(float4*)&Bs[brow][bcol4] = b4;
        __syncthreads();

        #pragma unroll
        for (int k = 0; k < 8; k++) {
            float ra[8], rb[8];
            *(float4*)&ra[0] = *(const float4*)&As[k][ty * 8];
            *(float4*)&ra[4] = *(const float4*)&As[k][ty * 8 + 4];
            *(float4*)&rb[0] = *(const float4*)&Bs[k][tx * 8];
            *(float4*)&rb[4] = *(const float4*)&Bs[k][tx * 8 + 4];
            #pragma unroll
            for (int i = 0; i < 8; i++)
                #pragma unroll
                for (int j = 0; j < 8; j++)
                    acc[i][j] = fmaf(ra[i], rb[j], acc[i][j]);
        }
        __syncthreads();
    }

    float bb0[8];
    #pragma unroll
    for (int j = 0; j < 8; j++)
        bb0[j] = bias ? bias[col0 + tx * 8 + j] : 0.0f;

    #pragma unroll
    for (int i = 0; i < 8; i++) {
        long long r = row0 + ty * 8 + i;
        float4 v0, v1;
        v0.x = acc[i][0] + bb0[0]; v0.y = acc[i][1] + bb0[1];
        v0.z = acc[i][2] + bb0[2]; v0.w = acc[i][3] + bb0[3];
        v1.x = acc[i][4] + bb0[4]; v1.y = acc[i][5] + bb0[5];
        v1.z = acc[i][6] + bb0[6]; v1.w = acc[i][7] + bb0[7];
        *(float4*)&C[r * N + col0 + tx * 8]     = v0;
        *(float4*)&C[r * N + col0 + tx * 8 + 4] = v1;
    }
}

// ---------------------------------------------------------------------------
// Fused scores kernel. Block = (batch b, 4 query positions) -> full 32x512
// score tile (rows = (q_local, w), cols = all 512 keys). Computes Q.K^T,
// masks, softmaxes over keys in-register (each row lives in one warp), then
// writes the contiguous prob matrix P (for the P@V GEMM) and the strided
// att output [b][q][k][w].
// Thread map: 256 thr = 8 warps; warp ty owns rows ty*4..ty*4+3 fully;
// lane tx owns columns {g*128 + tx*4 + j : g<4, j<4}.
// ---------------------------------------------------------------------------
__global__ __launch_bounds__(256)
void attn_scores_kernel(const float* __restrict__ Q, const float* __restrict__ Kmat,
                        const unsigned char* __restrict__ cmask,
                        const unsigned char* __restrict__ words,
                        float* __restrict__ P, float* __restrict__ att) {
    const int b = blockIdx.y;
    const int q0 = blockIdx.x * 4;

    const float* Qb = Q    + ((long long)(b * SS + q0) * WW) * DIN;  // 32 rows x 512
    const float* Kb = Kmat + (long long)b * SS * DIN;                // 512 rows x 512

    __shared__ float Qs[16][33];
    __shared__ float Ks[16][516];

    const int tid = threadIdx.x;
    const int tx = tid & 31, ty = tid >> 5;

    float acc[4][16];
    #pragma unroll
    for (int i = 0; i < 4; i++)
        #pragma unroll
        for (int j = 0; j < 16; j++) acc[i][j] = 0.0f;

    for (int d0 = 0; d0 < DIN; d0 += 16) {
        // Qs: 32 rows x 16 d (transposed)
        {
            int r = tid >> 3, c2 = (tid & 7) * 2;
            float2 v = *(const float2*)&Qb[(long long)r * DIN + d0 + c2];
            Qs[c2][r] = v.x;
            Qs[c2 + 1][r] = v.y;
        }
        // Ks: 512 keys x 16 d (transposed)
        #pragma unroll
        for (int it = 0; it < 8; it++) {
            int s = tid + it * 256;          // 2048 float4 slots
            int kk = s >> 2, dg = (s & 3) * 4;
            float4 v = *(const float4*)&Kb[(long long)kk * DIN + d0 + dg];
            Ks[dg + 0][kk] = v.x;
            Ks[dg + 1][kk] = v.y;
            Ks[dg + 2][kk] = v.z;
            Ks[dg + 3][kk] = v.w;
        }
        __syncthreads();

        #pragma unroll
        for (int d = 0; d < 16; d++) {
            float qv[4];
            #pragma unroll
            for (int i = 0; i < 4; i++) qv[i] = Qs[d][ty * 4 + i];
            #pragma unroll
            for (int g = 0; g < 4; g++) {
                float4 kv = *(const float4*)&Ks[d][g * 128 + tx * 4];
                #pragma unroll
                for (int i = 0; i < 4; i++) {
                    acc[i][g * 4 + 0] = fmaf(qv[i], kv.x, acc[i][g * 4 + 0]);
                    acc[i][g * 4 + 1] = fmaf(qv[i], kv.y, acc[i][g * 4 + 1]);
                    acc[i][g * 4 + 2] = fmaf(qv[i], kv.z, acc[i][g * 4 + 2]);
                    acc[i][g * 4 + 3] = fmaf(qv[i], kv.w, acc[i][g * 4 + 3]);
                }
            }
        }
        __syncthreads();
    }

    const float scale = 1.0f / sqrtf((float)DIN);
    // Key-side mask bits for this lane's 16 columns (same for every row)
    unsigned char wmk[16];
    #pragma unroll
    for (int g = 0; g < 4; g++)
        #pragma unroll
        for (int j = 0; j < 4; j++)
            wmk[g * 4 + j] = words[b * SS + g * 128 + tx * 4 + j];

    #pragma unroll
    for (int i = 0; i < 4; i++) {
        int r = ty * 4 + i;                             // 0..31 within tile
        int gr = (b * SS + q0) * WW + r;                // global (q,w) row
        unsigned char cm = cmask[gr];

        float mx = -3.0e38f;
        #pragma unroll
        for (int c = 0; c < 16; c++) {
            float s = acc[i][c] * scale;
            s = (cm && wmk[c]) ? s : -1e9f;
            acc[i][c] = s;
            mx = fmaxf(mx, s);
        }
        #pragma unroll
        for (int o = 16; o > 0; o >>= 1)
            mx = fmaxf(mx, __shfl_xor_sync(0xffffffffu, mx, o));

        float sum = 0.0f;
        #pragma unroll
        for (int c = 0; c < 16; c++) {
            float e = __expf(acc[i][c] - mx);
            acc[i][c] = e;
            sum += e;
        }
        #pragma unroll
        for (int o = 16; o > 0; o >>= 1)
            sum += __shfl_xor_sync(0xffffffffu, sum, o);
        float inv = 1.0f / sum;

        // P: contiguous [b][(q,w)][k] (coalesced float4 per g-group)
        long long prow = ((long long)b * (SS * WW) + (q0 * WW + r)) * SS;
        #pragma unroll
        for (int g = 0; g < 4; g++) {
            float4 o4;
            o4.x = acc[i][g * 4 + 0] * inv;
            o4.y = acc[i][g * 4 + 1] * inv;
            o4.z = acc[i][g * 4 + 2] * inv;
            o4.w = acc[i][g * 4 + 3] * inv;
            *(float4*)&P[prow + g * 128 + tx * 4] = o4;
            acc[i][g * 4 + 0] = o4.x; acc[i][g * 4 + 1] = o4.y;
            acc[i][g * 4 + 2] = o4.z; acc[i][g * 4 + 3] = o4.w;
        }
        // att: [b][q][k][w] (strided; element stores)
        if (att) {
            int q = q0 + (r >> 3), w = r & 7;
            long long abase = (((long long)b * SS + q) * SS) * WW + w;
            #pragma unroll
            for (int g = 0; g < 4; g++)
                #pragma unroll
                for (int j = 0; j < 4; j++) {
                    int k = g * 128 + tx * 4 + j;
                    att[abase + (long long)k * WW] = acc[i][g * 4 + j];
                }
        }
    }
}

// ---------------------------------------------------------------------------
extern "C" void kernel_launch(void* const* d_in, const int* in_sizes, int n_in,
                              void* d_out, int out_size) {
    const float* query = (const float*)d_in[0];
    const float* data  = (const float*)d_in[1];
    const void*  maskr = d_in[2];
    const float* Wq = (const float*)d_in[3];
    const float* bq = (const float*)d_in[4];
    const float* Wk = (const float*)d_in[5];
    const float* bk = (const float*)d_in[6];
    const float* Wv = (const float*)d_in[7];
    const float* bv = (const float*)d_in[8];
    const float* Wz = (const float*)d_in[9];
    const float* bz = (const float*)d_in[10];

    float* out = (float*)d_out;
    const long long zs_elems  = (long long)BB * SS * WW * DOUT;  // 33,554,432
    const long long att_elems = (long long)BB * SS * SS * WW;    // 33,554,432
    float* att = ((long long)out_size >= zs_elems + att_elems) ? out + zs_elems : nullptr;

    float *Qp, *Kp, *Vp, *Pp;
    unsigned char *cm, *wm;
    cudaGetSymbolAddress((void**)&Qp, g_Q);
    cudaGetSymbolAddress((void**)&Kp, g_K);
    cudaGetSymbolAddress((void**)&Vp, g_V);
    cudaGetSymbolAddress((void**)&Pp, g_P);
    cudaGetSymbolAddress((void**)&cm, g_cmask);
    cudaGetSymbolAddress((void**)&wm, g_words);

    // 0) classify mask dtype, normalize to bytes + key-side any() mask
    detect_mask_kernel<<<1, 1>>>((const unsigned int*)maskr);
    normalize_mask_kernel<<<(BB * SS + 255) / 256, 256>>>(maskr, cm, wm);

    // 1) Q projection: [65536,256] @ [256,512] + bq -> g_Q
    sgemm_bias<<<dim3(DIN / 128, (BB * SS * WW) / 128, 1), 256>>>(
        query, Wq, bq, Qp, BB * SS * WW, DIN, DQ, 0, 0, 0);
    // 2) K projection: [8192,512] @ [512,512] + bk -> g_K
    sgemm_bias<<<dim3(DIN / 128, (BB * SS) / 128, 1), 256>>>(
        data, Wk, bk, Kp, BB * SS, DIN, DIN, 0, 0, 0);
    // 3) V projection -> g_V
    sgemm_bias<<<dim3(DOUT / 128, (BB * SS) / 128, 1), 256>>>(
        data, Wv, bv, Vp, BB * SS, DOUT, DIN, 0, 0, 0);

    // 4) scores + mask + softmax -> P (and att region of d_out)
    attn_scores_kernel<<<dim3(SS / 4, BB), 256>>>(Qp, Kp, cm, wm, Pp, att);

    // 5) Z1[b] = P[b] @ V[b]   (batched over grid.z; reuse g_Q as Z1)
    sgemm_bias<<<dim3(DOUT / 128, (SS * WW) / 128, BB), 256>>>(
        Pp, Vp, nullptr, Qp, SS * WW, DOUT, SS,
        (long long)SS * WW * SS, (long long)SS * DIN, (long long)SS * WW * DOUT);

    // 6) zs = Z1 @ Wz + bz -> d_out (first zs_elems floats)
    sgemm_bias<<<dim3(DOUT / 128, (BB * SS * WW) / 128, 1), 256>>>(
        Qp, Wz, bz, out, BB * SS * WW, DOUT, DOUT, 0, 0, 0);
}

// round 5
// speedup vs baseline: 2.7131x; 2.7097x over previous
#include <cuda_runtime.h>
#include <cuda_fp16.h>
#include <math.h>
#include <stdint.h>

#define BB   16
#define SS   512
#define WW   8
#define DQ   256
#define DIN  512
#define DOUT 512

// ---------------- device scratch (allocation-free) ----------------
static __device__ __align__(1024) float g_Q[(size_t)BB*SS*WW*DIN];  // Qproj; reused as Z1
static __device__ __align__(1024) float g_K[(size_t)BB*SS*DIN];
static __device__ __align__(1024) float g_VT[(size_t)BB*DIN*SS];   // V^T per batch [z][s]
static __device__ __align__(1024) float g_P[(size_t)BB*SS*WW*SS];  // scores, then probs (in-place)
static __device__ __align__(1024) float g_WqT[DIN*DQ];
static __device__ __align__(1024) float g_WkT[DIN*DIN];
static __device__ __align__(1024) float g_WvT[DOUT*DIN];
static __device__ __align__(1024) float g_WzT[DOUT*DOUT];
static __device__ unsigned char g_cmask[BB*SS*WW];
static __device__ unsigned char g_words[BB*SS];
static __device__ int g_mask_mode;

// ---------------- low-level helpers (sm_80+ family features only) ----------------
__device__ __forceinline__ uint32_t smem_u32(const void* p) {
    uint32_t a;
    asm("{ .reg .u64 t; cvta.to.shared.u64 t, %1; cvt.u32.u64 %0, t; }" : "=r"(a) : "l"(p));
    return a;
}
__device__ __forceinline__ void ldsm4(uint32_t* r, uint32_t addr) {
    asm volatile("ldmatrix.sync.aligned.m8n8.x4.shared.b16 {%0,%1,%2,%3}, [%4];\n"
        : "=r"(r[0]), "=r"(r[1]), "=r"(r[2]), "=r"(r[3]) : "r"(addr));
}
__device__ __forceinline__ void mma16816(float* c, const uint32_t* a, const uint32_t* b) {
    asm volatile(
        "mma.sync.aligned.m16n8k16.row.col.f32.f16.f16.f32 "
        "{%0,%1,%2,%3}, {%4,%5,%6,%7}, {%8,%9}, {%0,%1,%2,%3};\n"
        : "+f"(c[0]), "+f"(c[1]), "+f"(c[2]), "+f"(c[3])
        : "r"(a[0]), "r"(a[1]), "r"(a[2]), "r"(a[3]), "r"(b[0]), "r"(b[1]));
}
__device__ __forceinline__ uint32_t pack2(__half a, __half b) {
    __half2 h = __halves2half2(a, b);
    return *(uint32_t*)&h;
}
// fp32 -> (hi, lo) fp16 split, 4 elems; hi plane + lo plane 8B stores
__device__ __forceinline__ void split_sts(char* hp, char* lp, float4 v) {
    __half h0 = __float2half_rn(v.x), h1 = __float2half_rn(v.y);
    __half h2 = __float2half_rn(v.z), h3 = __float2half_rn(v.w);
    __half l0 = __float2half_rn(v.x - __half2float(h0));
    __half l1 = __float2half_rn(v.y - __half2float(h1));
    __half l2 = __float2half_rn(v.z - __half2float(h2));
    __half l3 = __float2half_rn(v.w - __half2float(h3));
    *(uint2*)hp = make_uint2(pack2(h0, h1), pack2(h2, h3));
    *(uint2*)lp = make_uint2(pack2(l0, l1), pack2(l2, l3));
}

// ---------------- split-fp16 HMMA GEMM: C[M,N] = A[M,K] @ B[N,K]^T ----------------
// BM=128, BN=256, BK=32, 256 threads (8 warps, 2x4 grid, 64x64 warp tile).
// SMEM stage: A hi/lo planes 128x40 halves (80B rows), B hi/lo 256x40. 2 stages.
#define ROWB   80
#define A_PL   10240
#define B_PL   20480
#define STAGEB 61440

__device__ __forceinline__ void gemm_prefetch(const float* A, long long lda,
                                              const float* B, long long ldb,
                                              int kt, int tid, float4* pa, float4* pb) {
    #pragma unroll
    for (int it = 0; it < 4; it++) {
        int s = tid + it * 256, r = s >> 3, c = (s & 7) * 4;
        pa[it] = *(const float4*)(A + (long long)r * lda + kt + c);
    }
    #pragma unroll
    for (int it = 0; it < 8; it++) {
        int s = tid + it * 256, r = s >> 3, c = (s & 7) * 4;
        pb[it] = *(const float4*)(B + (long long)r * ldb + kt + c);
    }
}
__device__ __forceinline__ void gemm_sts(char* dsm, int stage, int tid,
                                         const float4* pa, const float4* pb) {
    char* base = dsm + stage * STAGEB;
    #pragma unroll
    for (int it = 0; it < 4; it++) {
        int s = tid + it * 256, r = s >> 3, c = (s & 7) * 4;
        split_sts(base + r * ROWB + c * 2, base + A_PL + r * ROWB + c * 2, pa[it]);
    }
    char* bb = base + 2 * A_PL;
    #pragma unroll
    for (int it = 0; it < 8; it++) {
        int s = tid + it * 256, r = s >> 3, c = (s & 7) * 4;
        split_sts(bb + r * ROWB + c * 2, bb + B_PL + r * ROWB + c * 2, pb[it]);
    }
}
__device__ __forceinline__ void gemm_compute(uint32_t sb, int wm, int wn, int lane, float* acc) {
    const uint32_t Ah = sb, Al = sb + A_PL, Bh = sb + 2 * A_PL, Bl = sb + 2 * A_PL + B_PL;
    const int mrow = (lane & 7) + ((lane >> 3) & 1) * 8, akcol = ((lane >> 4) & 1) * 8;
    const int nrow = (lane & 7) + ((lane >> 4) & 1) * 8, bkcol = ((lane >> 3) & 1) * 8;
    #pragma unroll
    for (int ks = 0; ks < 2; ks++) {
        const int k0 = ks * 16;
        uint32_t bfh[16], bfl[16];
        #pragma unroll
        for (int np = 0; np < 4; np++) {
            uint32_t off = (uint32_t)((wn * 64 + np * 16 + nrow) * ROWB + (k0 + bkcol) * 2);
            ldsm4(&bfh[np * 4], Bh + off);   // non-trans: [N][K] k-contiguous == mma "col" B
            ldsm4(&bfl[np * 4], Bl + off);
        }
        #pragma unroll
        for (int mi = 0; mi < 4; mi++) {
            uint32_t off = (uint32_t)((wm * 64 + mi * 16 + mrow) * ROWB + (k0 + akcol) * 2);
            uint32_t ah[4], al[4];
            ldsm4(ah, Ah + off);
            ldsm4(al, Al + off);
            #pragma unroll
            for (int ni = 0; ni < 8; ni++) {
                float* c = acc + (mi * 8 + ni) * 4;
                mma16816(c, ah, &bfh[ni * 2]);   // hi*hi
                mma16816(c, al, &bfh[ni * 2]);   // lo*hi
                mma16816(c, ah, &bfl[ni * 2]);   // hi*lo
            }
        }
    }
}

__global__ __launch_bounds__(256, 1)
void hgemm(const float* __restrict__ A, const float* __restrict__ B,
           const float* __restrict__ colbias, const float* __restrict__ rowbias,
           float* __restrict__ C, int K,
           long long lda, long long ldb, long long ldc,
           long long sAb, long long sBb, long long sCb)
{
    extern __shared__ char dsm[];
    const int tid = threadIdx.x, wid = tid >> 5, lane = tid & 31;
    const int wm = wid & 1, wn = wid >> 1;

    A += (long long)blockIdx.z * sAb + (long long)blockIdx.y * 128 * lda;
    B += (long long)blockIdx.z * sBb + (long long)blockIdx.x * 256 * ldb;
    C += (long long)blockIdx.z * sCb;

    float acc[128];
    #pragma unroll
    for (int i = 0; i < 128; i++) acc[i] = 0.0f;

    float4 pa[4], pb[8];
    gemm_prefetch(A, lda, B, ldb, 0, tid, pa, pb);
    gemm_sts(dsm, 0, tid, pa, pb);
    __syncthreads();

    const uint32_t sbase = smem_u32(dsm);
    const int NC = K >> 5;
    for (int i = 0; i < NC; i++) {
        if (i + 1 < NC) gemm_prefetch(A, lda, B, ldb, (i + 1) * 32, tid, pa, pb);
        gemm_compute(sbase + (i & 1) * STAGEB, wm, wn, lane, acc);
        if (i + 1 < NC) gemm_sts(dsm, (i + 1) & 1, tid, pa, pb);
        __syncthreads();
    }

    // epilogue: c0: (r, c), c1: (r, c+1), c2: (r+8, c), c3: (r+8, c+1)
    const long long wr = (long long)blockIdx.y * 128 + wm * 64;
    const long long wc = (long long)blockIdx.x * 256 + wn * 64;
    #pragma unroll
    for (int mi = 0; mi < 4; mi++) {
        long long r0 = wr + mi * 16 + (lane >> 2);
        float rb0 = rowbias ? rowbias[r0]     : 0.0f;
        float rb1 = rowbias ? rowbias[r0 + 8] : 0.0f;
        #pragma unroll
        for (int ni = 0; ni < 8; ni++) {
            long long c0 = wc + ni * 8 + (lane & 3) * 2;
            float cb0 = 0.0f, cb1 = 0.0f;
            if (colbias) { float2 cb = *(const float2*)(colbias + c0); cb0 = cb.x; cb1 = cb.y; }
            const float* a = acc + (mi * 8 + ni) * 4;
            *(float2*)(C + r0 * ldc + c0)       = make_float2(a[0] + cb0 + rb0, a[1] + cb1 + rb0);
            *(float2*)(C + (r0 + 8) * ldc + c0) = make_float2(a[2] + cb0 + rb1, a[3] + cb1 + rb1);
        }
    }
}

// ---------------- fused mask+softmax+normalize + att transpose ----------------
__global__ __launch_bounds__(256)
void smx_att(float* __restrict__ S, const unsigned char* __restrict__ cmask,
             const unsigned char* __restrict__ words, float* __restrict__ att)
{
    __shared__ float tile[8][521];
    __shared__ unsigned char words_s[512];
    const int b = blockIdx.y, q = blockIdx.x;
    const int tid = threadIdx.x, w = tid >> 5, lane = tid & 31;
    for (int i = tid; i < 512; i += 256) words_s[i] = words[b * 512 + i];
    __syncthreads();

    const long long base8 = ((long long)b * 512 + q) * 8;
    float* row = S + (base8 + w) * 512;
    const bool cmb = cmask[base8 + w] != 0;
    const float scale = 0.04419417382415922f;  // 1/sqrt(512)

    float v[16];
    float mx = -3.0e38f;
    #pragma unroll
    for (int i = 0; i < 4; i++) {
        float4 x = *(const float4*)(row + i * 128 + lane * 4);
        float t[4] = {x.x, x.y, x.z, x.w};
        #pragma unroll
        for (int j = 0; j < 4; j++) {
            int k = i * 128 + lane * 4 + j;
            float s = t[j] * scale;
            s = (cmb && words_s[k]) ? s : -1e9f;
            v[i * 4 + j] = s;
            mx = fmaxf(mx, s);
        }
    }
    #pragma unroll
    for (int o = 16; o > 0; o >>= 1) mx = fmaxf(mx, __shfl_xor_sync(0xffffffffu, mx, o));
    float sum = 0.0f;
    #pragma unroll
    for (int i = 0; i < 16; i++) { float e = __expf(v[i] - mx); v[i] = e; sum += e; }
    #pragma unroll
    for (int o = 16; o > 0; o >>= 1) sum += __shfl_xor_sync(0xffffffffu, sum, o);
    const float inv = 1.0f / sum;

    #pragma unroll
    for (int i = 0; i < 4; i++) {
        float4 p = make_float4(v[i*4]*inv, v[i*4+1]*inv, v[i*4+2]*inv, v[i*4+3]*inv);
        *(float4*)(row + i * 128 + lane * 4) = p;
        int k = i * 128 + lane * 4;
        tile[w][k] = p.x; tile[w][k+1] = p.y; tile[w][k+2] = p.z; tile[w][k+3] = p.w;
    }
    if (att) {
        __syncthreads();
        float* obase = att + base8 * 512;
        #pragma unroll
        for (int it = 0; it < 16; it++) {
            int idx = tid + it * 256;
            obase[idx] = tile[idx & 7][idx >> 3];
        }
    }
}

// ---------------- weight transpose ----------------
__global__ void transpose32(const float* __restrict__ in, float* __restrict__ out,
                            int R, int C) {
    __shared__ float t[32][33];
    int c0 = blockIdx.x * 32, r0 = blockIdx.y * 32;
    int x = threadIdx.x, y = threadIdx.y;
    #pragma unroll
    for (int j = 0; j < 32; j += 8)
        t[y + j][x] = in[(long long)(r0 + y + j) * C + c0 + x];
    __syncthreads();
    #pragma unroll
    for (int j = 0; j < 32; j += 8)
        out[(long long)(c0 + y + j) * R + r0 + x] = t[x][y + j];
}

// ---------------- mask handling ----------------
__global__ void detect_mask_kernel(const unsigned int* __restrict__ m) {
    if (blockIdx.x == 0 && threadIdx.x == 0) {
        bool all01 = true, allf = true;
        for (int i = 0; i < 1024; i++) {
            unsigned int v = m[i];
            if (!(v == 0u || v == 1u)) all01 = false;
            if (!(v == 0u || v == 0x3F800000u)) allf = false;
        }
        g_mask_mode = all01 ? 1 : (allf ? 0 : 2);
    }
}
__global__ void normalize_mask_kernel(const void* __restrict__ m,
                                      unsigned char* __restrict__ cmask,
                                      unsigned char* __restrict__ words) {
    int idx = blockIdx.x * blockDim.x + threadIdx.x;
    if (idx >= BB * SS) return;
    int mode = g_mask_mode;
    unsigned char any = 0;
    #pragma unroll
    for (int w = 0; w < WW; w++) {
        int e = idx * WW + w;
        unsigned char v;
        if (mode == 1)      v = (((const int*)m)[e] != 0);
        else if (mode == 0) v = (((const float*)m)[e] != 0.0f);
        else                v = (((const unsigned char*)m)[e] != 0);
        cmask[e] = v;
        any |= v;
    }
    words[idx] = any;
}

// ---------------- launch ----------------
extern "C" void kernel_launch(void* const* d_in, const int* in_sizes, int n_in,
                              void* d_out, int out_size) {
    const float* query = (const float*)d_in[0];
    const float* data  = (const float*)d_in[1];
    const void*  maskr = d_in[2];
    const float* Wq = (const float*)d_in[3];
    const float* bq = (const float*)d_in[4];
    const float* Wk = (const float*)d_in[5];
    const float* bk = (const float*)d_in[6];
    const float* Wv = (const float*)d_in[7];
    const float* bv = (const float*)d_in[8];
    const float* Wz = (const float*)d_in[9];
    const float* bz = (const float*)d_in[10];

    float* out = (float*)d_out;
    const long long zs_elems  = (long long)BB * SS * WW * DOUT;
    const long long att_elems = (long long)BB * SS * SS * WW;
    float* att = ((long long)out_size >= zs_elems + att_elems) ? out + zs_elems : nullptr;

    float *Qp, *Kp, *VTp, *Pp, *wqt, *wkt, *wvt, *wzt;
    unsigned char *cm, *wm;
    cudaGetSymbolAddress((void**)&Qp, g_Q);
    cudaGetSymbolAddress((void**)&Kp, g_K);
    cudaGetSymbolAddress((void**)&VTp, g_VT);
    cudaGetSymbolAddress((void**)&Pp, g_P);
    cudaGetSymbolAddress((void**)&wqt, g_WqT);
    cudaGetSymbolAddress((void**)&wkt, g_WkT);
    cudaGetSymbolAddress((void**)&wvt, g_WvT);
    cudaGetSymbolAddress((void**)&wzt, g_WzT);
    cudaGetSymbolAddress((void**)&cm, g_cmask);
    cudaGetSymbolAddress((void**)&wm, g_words);

    const int SMEM = 2 * STAGEB;   // 122880
    cudaFuncSetAttribute(hgemm, cudaFuncAttributeMaxDynamicSharedMemorySize, SMEM);

    detect_mask_kernel<<<1, 1>>>((const unsigned int*)maskr);
    normalize_mask_kernel<<<(BB * SS + 255) / 256, 256>>>(maskr, cm, wm);

    transpose32<<<dim3(DIN/32, DQ/32),   dim3(32,8)>>>(Wq, wqt, DQ,  DIN);
    transpose32<<<dim3(DIN/32, DIN/32),  dim3(32,8)>>>(Wk, wkt, DIN, DIN);
    transpose32<<<dim3(DOUT/32, DIN/32), dim3(32,8)>>>(Wv, wvt, DIN, DOUT);
    transpose32<<<dim3(DOUT/32, DOUT/32),dim3(32,8)>>>(Wz, wzt, DOUT, DOUT);

    // Qproj: [65536,512] = query[65536,256] @ wqt[512,256]^T + bq
    hgemm<<<dim3(2, 512, 1), 256, SMEM>>>(query, wqt, bq, nullptr, Qp,
        DQ, DQ, DQ, DIN, 0, 0, 0);
    // Kproj: [8192,512] = data @ wkt^T + bk
    hgemm<<<dim3(2, 64, 1), 256, SMEM>>>(data, wkt, bk, nullptr, Kp,
        DIN, DIN, DIN, DIN, 0, 0, 0);
    // VT[b]: [512(z),512(s)] = wvt[z,din] @ data_b[s,din]^T + bv[z] (row bias)
    hgemm<<<dim3(2, 4, BB), 256, SMEM>>>(wvt, data, nullptr, bv, VTp,
        DIN, DIN, DIN, SS, 0, (long long)SS * DIN, (long long)DIN * SS);
    // scores[b]: [4096,512] = Qp_b @ Kp_b^T (scale applied in softmax)
    hgemm<<<dim3(2, 32, BB), 256, SMEM>>>(Qp, Kp, nullptr, nullptr, Pp,
        DIN, DIN, DIN, SS,
        (long long)SS * WW * DIN, (long long)SS * DIN, (long long)SS * WW * SS);
    // softmax + normalize (in-place) + att transpose
    smx_att<<<dim3(SS, BB), 256>>>(Pp, cm, wm, att);
    // Z1[b] = P_b @ VT_b^T  -> g_Q
    hgemm<<<dim3(2, 32, BB), 256, SMEM>>>(Pp, VTp, nullptr, nullptr, Qp,
        SS, SS, SS, DOUT,
        (long long)SS * WW * SS, (long long)DIN * SS, (long long)SS * WW * DOUT);
    // zs = Z1 @ wzt^T + bz -> d_out
    hgemm<<<dim3(2, 512, 1), 256, SMEM>>>(Qp, wzt, bz, nullptr, out,
        DOUT, DOUT, DOUT, DOUT, 0, 0, 0);
}